// round 4
// baseline (speedup 1.0000x reference)
#include <cuda_runtime.h>
#include <math.h>

// Problem constants
#define BB    64
#define TT    512
#define INSZ  512
#define HH    1024
#define OUTSZ 512
#define NG    4096          // 4*HH gate columns
#define BSEL  63            // only batch row 63 affects the output

#define NBLK  128           // persistent blocks (<=148 SMs, wave-1 co-resident)
#define NTHR  256

// ---------------------------------------------------------------------------
// Static device scratch. h vectors are cross-block shared -> all accesses via
// __ldcg/__stcg (L2). Cell state c is block-private -> lives in SMEM.
// ---------------------------------------------------------------------------
__device__ float g_h0[2][HH];
__device__ float g_h1[2][HH];
__device__ float g_hist[TT][HH];     // h1(t) history for the final dense

__device__ unsigned g_cnt = 0;
__device__ unsigned g_gen = 0;

__device__ __forceinline__ void gridbar() {
    __syncthreads();
    if (threadIdx.x == 0) {
        volatile unsigned* vgen = &g_gen;
        unsigned gen = *vgen;            // read generation BEFORE arriving
        __threadfence();                 // release my writes to L2
        if (atomicAdd(&g_cnt, 1u) == NBLK - 1) {
            atomicExch(&g_cnt, 0u);      // reset (atomic -> visible to L2 atomics)
            __threadfence();
            atomicAdd(&g_gen, 1u);       // release everyone
        } else {
            while (*vgen == gen) { }     // volatile spin (L2)
            __threadfence();
        }
    }
    __syncthreads();
}

__device__ __forceinline__ float sigf(float x) {
    return 1.0f / (1.0f + expf(-x));
}

// ---------------------------------------------------------------------------
// One LSTM cell GEMV for this block's 8 h-columns (32 gate cols), M=1.
// Thread layout: cg = tid&7 -> column group (gate g = cg>>1, 4 consecutive
// cols at hbase + (cg&1)*4), s = tid>>3 -> one of 32 K-slices.
// Partials reduced through SMEM; threads 0..7 run the gate epilogue.
// ---------------------------------------------------------------------------
template<int K>
__device__ __forceinline__ void gemv_cell(
    const float* __restrict__ W,      // (K, 4096) row-major
    const float* __restrict__ bias,   // (4096)
    const float* __restrict__ in_sh,  // staged input vector (K floats)
    float* __restrict__ red,          // smem scratch: 32*32 floats
    float* __restrict__ zf,           // smem scratch: 32 floats
    float* __restrict__ c_s,          // smem: 8 cell states (persistent)
    float* __restrict__ h_out,        // global: 8 floats at hbase
    float* __restrict__ hist_out)     // optional second h sink (or null)
{
    const int tid = threadIdx.x;
    const int cg  = tid & 7;
    const int s   = tid >> 3;
    const int hbase = blockIdx.x << 3;
    const int colbase = (cg >> 1) * HH + hbase + ((cg & 1) << 2);
    constexpr int KS = K / 32;

    float4 acc = make_float4(0.f, 0.f, 0.f, 0.f);
    const float* wp = W + (size_t)(s * KS) * NG + colbase;
    const float* ip = in_sh + s * KS;
#pragma unroll 8
    for (int k = 0; k < KS; k++) {
        float f = ip[k];
        float4 w4 = __ldg((const float4*)wp);
        wp += NG;
        acc.x = fmaf(f, w4.x, acc.x);
        acc.y = fmaf(f, w4.y, acc.y);
        acc.z = fmaf(f, w4.z, acc.z);
        acc.w = fmaf(f, w4.w, acc.w);
    }
    ((float4*)red)[(s << 3) + cg] = acc;   // red[s][cg][e] = red[s*32 + cg*4 + e]
    __syncthreads();

    if (tid < 32) {                        // tid = cidx = g*8 + j
        float sum = 0.f;
#pragma unroll
        for (int ss = 0; ss < 32; ss++) sum += red[(ss << 5) + tid];
        int gate = tid >> 3, j = tid & 7;
        zf[tid] = sum + bias[gate * HH + hbase + j];
    }
    __syncthreads();

    if (tid < 8) {
        int j = tid;
        float zi = zf[j], zj = zf[8 + j], zff = zf[16 + j], zo = zf[24 + j];
        float cn = sigf(zff + 1.0f) * c_s[j] + sigf(zi) * tanhf(zj);
        c_s[j] = cn;
        float h = sigf(zo) * tanhf(cn);
        __stcg(h_out + j, h);
        if (hist_out) __stcg(hist_out + j, h);
    }
}

// ---------------------------------------------------------------------------
// Single persistent kernel: init, 512 x (layer0 | bar | layer1 | bar),
// then the final dense over the h1 history: out[t][o], t=0..511.
// ---------------------------------------------------------------------------
__global__ __launch_bounds__(NTHR) void lstm_persistent(
    const float* __restrict__ X,
    const float* __restrict__ state,
    const float* __restrict__ W0, const float* __restrict__ b0,
    const float* __restrict__ W1, const float* __restrict__ b1,
    const float* __restrict__ Wd, const float* __restrict__ bd,
    float* __restrict__ out)
{
    __shared__ __align__(16) float sp[4160];   // in_sh(2048) | red(1024) | zf(32); dense reuses 4096
    __shared__ float c0_s[8], c1_s[8];
    float* in_sh = sp;
    float* red   = sp + 2048;
    float* zf    = sp + 3072;

    const int tid   = threadIdx.x;
    const int hbase = blockIdx.x << 3;

    // ---- init from state row 63: [c0 | h0 | c1 | h1] ----
    const float* srow = state + (size_t)BSEL * 4 * HH;
    if (blockIdx.x == 0) {
        for (int i = tid; i < HH; i += NTHR) {
            __stcg(&g_h0[0][i], srow[HH + i]);
            __stcg(&g_h1[0][i], srow[3 * HH + i]);
        }
    }
    if (tid < 8) {
        c0_s[tid] = srow[hbase + tid];
        c1_s[tid] = srow[2 * HH + hbase + tid];
    }
    gridbar();

    // ---- time loop (batch row 63 only) ----
    const float* Xrow = X + (size_t)BSEL * TT * INSZ;
    int p = 0;
    for (int t = 0; t < TT; t++) {
        // phase A: layer 0, input = [x_t (512), h0_prev (1024)], K=1536
        const float* xt = Xrow + t * INSZ;
        if (tid < 128)
            ((float4*)in_sh)[tid] = __ldg((const float4*)xt + tid);
        ((float4*)(in_sh + 512))[tid] = __ldcg((const float4*)&g_h0[p][0] + tid);
        __syncthreads();
        gemv_cell<INSZ + HH>(W0, b0, in_sh, red, zf, c0_s,
                             &g_h0[p ^ 1][hbase], (float*)0);
        gridbar();

        // phase B: layer 1, input = [h0_cur (1024), h1_prev (1024)], K=2048
        ((float4*)in_sh)[tid]          = __ldcg((const float4*)&g_h0[p ^ 1][0] + tid);
        ((float4*)(in_sh + 1024))[tid] = __ldcg((const float4*)&g_h1[p][0] + tid);
        __syncthreads();
        gemv_cell<2 * HH>(W1, b1, in_sh, red, zf, c1_s,
                          &g_h1[p ^ 1][hbase], &g_hist[t][hbase]);
        gridbar();
        p ^= 1;
    }

    // ---- dense: out[t][o] = hist[t] @ Wd + bd, block owns 4 t-rows ----
    {
        int t0 = blockIdx.x << 2;
#pragma unroll
        for (int r = 0; r < 4; r++)
            ((float4*)sp)[(r << 8) + tid] =
                __ldcg((const float4*)&g_hist[t0 + r][0] + tid);
        __syncthreads();

        int o2 = tid << 1;
        float b0v = bd[o2], b1v = bd[o2 + 1];
        float acc[4][2];
#pragma unroll
        for (int r = 0; r < 4; r++) { acc[r][0] = b0v; acc[r][1] = b1v; }
        const float* wp = Wd + o2;
#pragma unroll 4
        for (int k = 0; k < HH; k++) {
            float2 w2 = *(const float2*)wp; wp += OUTSZ;
#pragma unroll
            for (int r = 0; r < 4; r++) {
                float hv = sp[(r << 10) + k];
                acc[r][0] = fmaf(hv, w2.x, acc[r][0]);
                acc[r][1] = fmaf(hv, w2.y, acc[r][1]);
            }
        }
#pragma unroll
        for (int r = 0; r < 4; r++) {
            float2 o = make_float2(acc[r][0], acc[r][1]);
            *(float2*)(out + (size_t)(t0 + r) * OUTSZ + o2) = o;
        }
    }
}

// ---------------------------------------------------------------------------
// Launcher: exactly ONE kernel launch (graph-capturable, allocation-free).
// ---------------------------------------------------------------------------
extern "C" void kernel_launch(void* const* d_in, const int* in_sizes, int n_in,
                              void* d_out, int out_size)
{
    (void)in_sizes; (void)n_in; (void)out_size;
    const float* X     = (const float*)d_in[0];
    const float* state = (const float*)d_in[1];
    const float* W0    = (const float*)d_in[2];
    const float* b0    = (const float*)d_in[3];
    const float* W1    = (const float*)d_in[4];
    const float* b1    = (const float*)d_in[5];
    const float* Wd    = (const float*)d_in[6];
    const float* bd    = (const float*)d_in[7];

    lstm_persistent<<<NBLK, NTHR>>>(X, state, W0, b0, W1, b1, Wd, bd,
                                    (float*)d_out);
}